// round 16
// baseline (speedup 1.0000x reference)
#include <cuda_runtime.h>

// Problem constants (B=1, H=32, Q=1024, S=4096, D=128)
#define SEQ      4096
#define ROWS     32768      // B*H*Q rows of attn_weights
#define START    4
#define HEAVY    409        // int(4096*0.1)
#define RSTART   3687       // 4096 - min(409,512)
#define NCAND    3683       // RSTART - START
#define NKEEP    822        // 4 + 409 + 409
#define HEADS    32
#define NBLK     148        // one exact wave
#define NTHR     1024
#define NFIX     413        // START + recent rows (selection-independent)
#define TOTAL_F  (2*HEADS*NFIX*32)    // fixed-gather float4  = 845824
#define TOTAL_H  (2*HEADS*HEAVY*32)   // heavy-gather float4  = 837632
#define FSTRIDE  (NBLK*NTHR)          // 151552 (6 chunks cover TOTAL_F)
#define SETCAP   512        // max selected-bin tie set (expected ~5-20)

// Scratch. g_sums is atomically accumulated so it MUST be zero at entry:
// in k_tail, the last block to FINISH LOADING g_sums re-zeroes it at its
// end (arrive counter, no waiting). g_done reset by that same block.
__device__ double g_sums[SEQ];
__device__ int    g_done;

// ================= Kernel 1: column sums (512 MB PURE READ stream) =========
// 148 blocks, contiguous row range each (measured ~80us @ ~83% DRAM —
// at the practical HBM ceiling). Thread t owns columns [4t,4t+4) via
// float4; 8 front-batched LDG.128 (MLP=8); __ldcs (no reuse). fp32 over 32
// rows flushed into fp64 keeps the mean accurate to ~1e-8 rel (top-k
// boundary gap ~1e-5); fp64 atomicAdd ordering noise ~1e-13 — selection
// identical to reference (rel_err 0.0 in all rounds).
__global__ void __launch_bounds__(NTHR, 1) k_colsum(const float* __restrict__ w) {
    const int t = threadIdx.x;
    const int b = blockIdx.x;
    const int r0 = (int)((long long)ROWS * b / NBLK);
    const int r1 = (int)((long long)ROWS * (b + 1) / NBLK);
    const float4* __restrict__ w4 = (const float4*)w + t;
    double a0 = 0, a1 = 0, a2 = 0, a3 = 0;
    float  c0 = 0, c1 = 0, c2 = 0, c3 = 0;
    int row = r0, grp = 0;
    for (; row + 8 <= r1; row += 8) {
        float4 v[8];
        #pragma unroll
        for (int k = 0; k < 8; k++)
            v[k] = __ldcs(&w4[(size_t)(row + k) * 1024]);
        float s0x = (v[0].x + v[1].x) + (v[2].x + v[3].x);
        float s1x = (v[4].x + v[5].x) + (v[6].x + v[7].x);
        float s0y = (v[0].y + v[1].y) + (v[2].y + v[3].y);
        float s1y = (v[4].y + v[5].y) + (v[6].y + v[7].y);
        float s0z = (v[0].z + v[1].z) + (v[2].z + v[3].z);
        float s1z = (v[4].z + v[5].z) + (v[6].z + v[7].z);
        float s0w = (v[0].w + v[1].w) + (v[2].w + v[3].w);
        float s1w = (v[4].w + v[5].w) + (v[6].w + v[7].w);
        c0 += s0x + s1x;  c1 += s0y + s1y;
        c2 += s0z + s1z;  c3 += s0w + s1w;
        if (++grp == 4) {                 // flush every 32 rows
            a0 += c0; a1 += c1; a2 += c2; a3 += c3;
            c0 = c1 = c2 = c3 = 0.f; grp = 0;
        }
    }
    for (; row < r1; row++) {
        float4 v = __ldcs(&w4[(size_t)row * 1024]);
        c0 += v.x; c1 += v.y; c2 += v.z; c3 += v.w;
    }
    a0 += c0; a1 += c1; a2 += c2; a3 += c3;
    int s = 4 * t;
    atomicAdd(&g_sums[s + 0], a0);
    atomicAdd(&g_sums[s + 1], a1);
    atomicAdd(&g_sums[s + 2], a2);
    atomicAdd(&g_sums[s + 3], a3);
}

// Fixed-gather addressing (sinks + recent window, selection-independent).
__device__ __forceinline__ bool fg_addr(int v,
                                        const float4* __restrict__ keys,
                                        const float4* __restrict__ vals,
                                        const float4** src, size_t* oi) {
    if (v >= TOTAL_F) return false;
    int d4  = v & 31;
    int row = v >> 5;
    int tensor = row / (HEADS * NFIX);
    int rem = row - tensor * (HEADS * NFIX);
    int h   = rem / NFIX;
    int p   = rem - h * NFIX;                 // 0..412
    int r   = (p < START) ? p : p + HEAVY;    // output row (keep order)
    int s   = (p < START) ? p : (RSTART + p - START);
    const float4* sp = tensor ? vals : keys;
    *src = &sp[(((size_t)h * SEQ + s) << 5) + d4];
    *oi  = (((size_t)(tensor * HEADS + h) * NKEEP + r) << 5) + d4;
    return true;
}

// ==== Kernel 2: select (shift-binned histogram) || pipelined fixed gather ==
// Select logic identical to R15 (proven): ONE shift-binned histogram,
// monotonic in the u64 key; tie subset exact-ranked with the reference
// comparator (value desc, index asc) == jax.lax.top_k.
// Each thread's 6 fixed-gather float4s are software-pipelined between the
// select phases: load chunk k, run a phase, store k / load k+1.
__global__ void __launch_bounds__(NTHR, 1)
k_tail(const float4* __restrict__ keys,
       const float4* __restrict__ vals,
       float4* __restrict__ out) {
    __shared__ unsigned long long sj[NCAND];
    __shared__ int  hist[2048];
    __shared__ int  s_keep[NKEEP];
    __shared__ int  warpsum[32];
    __shared__ unsigned long long redmin[32], redmax[32];
    __shared__ unsigned long long s_kmin;
    __shared__ int  s_shift;
    __shared__ int  s_bin, s_R, s_setcnt, s_zero;
    __shared__ int  s_setidx[SETCAP];
    __shared__ unsigned char s_take[SETCAP];

    const int t = threadIdx.x;
    const int b = blockIdx.x;
    const int lane = t & 31, w = t >> 5;

    // Fixed-gather pipeline state.
    int fgv = b * NTHR + t;
    const float4* fgs; size_t fgo; float4 fgd; bool fgok;
    #define FG_LOAD()  do { fgok = fg_addr(fgv, keys, vals, &fgs, &fgo); \
                            if (fgok) fgd = __ldcs(fgs); } while (0)
    #define FG_STORE() do { if (fgok) out[fgo] = fgd; fgv += FSTRIDE; } while (0)

    // ---- load candidate sums + zero hist (chunk 0 load issued first) ------
    FG_LOAD();                                   // chunk 0 in flight
    for (int i = t; i < 2048; i += NTHR) hist[i] = 0;
    for (int k = t; k < NCAND; k += NTHR)
        sj[k] = __double_as_longlong(__ldcg(&g_sums[START + k]));
    if (t == 0) s_setcnt = 0;
    __syncthreads();
    if (t == 0) {
        __threadfence();
        s_zero = (atomicAdd(&g_done, 1) == NBLK - 1) ? 1 : 0;
    }

    // ---- min/max reduce -> shift ------------------------------------------
    {
        unsigned long long mn = ~0ULL, mx = 0ULL;
        for (int k = t; k < NCAND; k += NTHR) {
            unsigned long long key = sj[k];
            mn = min(mn, key); mx = max(mx, key);
        }
        #pragma unroll
        for (int o = 16; o; o >>= 1) {
            mn = min(mn, __shfl_xor_sync(0xFFFFFFFFu, mn, o));
            mx = max(mx, __shfl_xor_sync(0xFFFFFFFFu, mx, o));
        }
        if (lane == 0) { redmin[w] = mn; redmax[w] = mx; }
        __syncthreads();
        if (w == 0) {
            mn = redmin[lane]; mx = redmax[lane];
            #pragma unroll
            for (int o = 16; o; o >>= 1) {
                mn = min(mn, __shfl_xor_sync(0xFFFFFFFFu, mn, o));
                mx = max(mx, __shfl_xor_sync(0xFFFFFFFFu, mx, o));
            }
            if (lane == 0) {
                s_kmin = mn;
                unsigned long long width = mx - mn;
                int bits = 64 - __clzll(width | 1ULL);
                s_shift = (bits > 11) ? (bits - 11) : 0;
            }
        }
        __syncthreads();
    }
    FG_STORE(); FG_LOAD();                       // chunk 0 -> out, chunk 1 in
    const unsigned long long kmin = s_kmin;
    const int sh = s_shift;
    #define BINOF(key) ((int)(((key) - kmin) >> sh))

    // ---- single 2048-bin histogram ----------------------------------------
    for (int k = t; k < NCAND; k += NTHR)
        atomicAdd(&hist[BINOF(sj[k])], 1);
    __syncthreads();
    FG_STORE(); FG_LOAD();                       // chunk 1 -> out, chunk 2 in

    // ---- suffix scan over bins (descending) -> threshold bin + residual R --
    {
        const int r0 = 2 * t, r1 = 2 * t + 1;
        const int v0 = hist[2047 - r0];
        const int v1 = hist[2047 - r1];
        const int pair = v0 + v1;
        int v = pair;
        #pragma unroll
        for (int o = 1; o < 32; o <<= 1) {
            int n = __shfl_up_sync(0xFFFFFFFFu, v, o);
            if (lane >= o) v += n;
        }
        if (lane == 31) warpsum[w] = v;
        __syncthreads();
        if (w == 0) {
            int s = warpsum[lane];
            #pragma unroll
            for (int o = 1; o < 32; o <<= 1) {
                int n = __shfl_up_sync(0xFFFFFFFFu, s, o);
                if (lane >= o) s += n;
            }
            warpsum[lane] = s;
        }
        __syncthreads();
        const int excl = v - pair + (w > 0 ? warpsum[w - 1] : 0);
        const int T0 = excl + v0;
        const int T1 = excl + pair;
        const int R = HEAVY;
        if (T0 - v0 < R && R <= T0) { s_bin = 2047 - r0; s_R = R - (T0 - v0); }
        if (T1 - v1 < R && R <= T1) { s_bin = 2047 - r1; s_R = R - (T1 - v1); }
        __syncthreads();
    }
    FG_STORE(); FG_LOAD();                       // chunk 2 -> out, chunk 3 in
    const int selbin = s_bin;
    const int R = s_R;

    // ---- exact tie subset within the threshold bin -------------------------
    for (int k = t; k < NCAND; k += NTHR) {
        if (BINOF(sj[k]) == selbin) {
            int p = atomicAdd(&s_setcnt, 1);
            if (p < SETCAP) s_setidx[p] = k;
        }
    }
    __syncthreads();
    FG_STORE(); FG_LOAD();                       // chunk 3 -> out, chunk 4 in
    const int setcnt = min(s_setcnt, SETCAP);
    if (w == 0) {
        for (int m = lane; m < setcnt; m += 32) {
            int im = s_setidx[m];
            unsigned long long km = sj[im];
            int rk = 0;
            for (int j = 0; j < setcnt; j++) {
                int ij = s_setidx[j];
                unsigned long long kj = sj[ij];
                rk += (kj > km || (kj == km && ij < im)) ? 1 : 0;
            }
            s_take[m] = (rk < R) ? 1 : 0;
        }
    }
    __syncthreads();
    FG_STORE(); FG_LOAD();                       // chunk 4 -> out, chunk 5 in

    // ---- build full sorted keep list ---------------------------------------
    // keep = [0..3] ++ heavy(sorted asc) ++ [3687..4095] (globally sorted)
    {
        int base = 4 * t;
        int f[4], loc = 0;
        #pragma unroll
        for (int k = 0; k < 4; k++) {
            int c = base + k;
            int fl = 0;
            if (c < NCAND) {
                int bc = BINOF(sj[c]);
                if (bc > selbin) fl = 1;
                else if (bc == selbin) {
                    for (int m = 0; m < setcnt; m++)
                        if (s_setidx[m] == c) { fl = s_take[m]; break; }
                }
            }
            f[k] = fl; loc += fl;
        }
        int v = loc;
        #pragma unroll
        for (int o = 1; o < 32; o <<= 1) {
            int n = __shfl_up_sync(0xFFFFFFFFu, v, o);
            if (lane >= o) v += n;
        }
        if (lane == 31) warpsum[w] = v;
        __syncthreads();
        if (w == 0) {
            int s = warpsum[lane];
            #pragma unroll
            for (int o = 1; o < 32; o <<= 1) {
                int n = __shfl_up_sync(0xFFFFFFFFu, s, o);
                if (lane >= o) s += n;
            }
            warpsum[lane] = s;
        }
        __syncthreads();
        int pos = START + v - loc + (w > 0 ? warpsum[w - 1] : 0);
        #pragma unroll
        for (int k = 0; k < 4; k++) {
            if (f[k]) { s_keep[pos] = START + base + k; pos++; }
        }
        if (t < START) s_keep[t] = t;
        if (t < SEQ - RSTART) s_keep[START + HEAVY + t] = RSTART + t;
    }
    FG_STORE();                                  // chunk 5 -> out (last fixed)
    __syncthreads();

    // ---- Phase D: heavy gather (27 MB), unroll-4 (proven form) ------------
    {
        const int stride = NBLK * NTHR;          // 151552
        int v = b * NTHR + t;
        for (; v + 3 * stride < TOTAL_H; v += 4 * stride) {
            float4 d[4];
            size_t oidx[4];
            #pragma unroll
            for (int k = 0; k < 4; k++) {
                int vv  = v + k * stride;
                int d4  = vv & 31;
                int row = vv >> 5;
                int tensor = row / (HEADS * HEAVY);
                int rem = row - tensor * (HEADS * HEAVY);
                int h   = rem / HEAVY;
                int q   = rem - h * HEAVY;       // heavy slot 0..408
                int s   = s_keep[START + q];
                const float4* __restrict__ src = tensor ? vals : keys;
                d[k] = __ldcs(&src[(((size_t)h * SEQ + s) << 5) + d4]);
                oidx[k] = (((size_t)(tensor * HEADS + h) * NKEEP + (START + q)) << 5) + d4;
            }
            #pragma unroll
            for (int k = 0; k < 4; k++) out[oidx[k]] = d[k];
        }
        for (; v < TOTAL_H; v += stride) {
            int d4  = v & 31;
            int row = v >> 5;
            int tensor = row / (HEADS * HEAVY);
            int rem = row - tensor * (HEADS * HEAVY);
            int h   = rem / HEAVY;
            int q   = rem - h * HEAVY;
            int s   = s_keep[START + q];
            const float4* __restrict__ src = tensor ? vals : keys;
            out[(((size_t)(tensor * HEADS + h) * NKEEP + (START + q)) << 5) + d4] =
                __ldcs(&src[(((size_t)h * SEQ + s) << 5) + d4]);
        }
    }

    // ---- epilogue: designated block re-zeroes g_sums for next call --------
    __syncthreads();
    if (s_zero) {
        for (int i = t; i < SEQ; i += NTHR) g_sums[i] = 0.0;
        if (t == 0) g_done = 0;
    }
    #undef BINOF
    #undef FG_LOAD
    #undef FG_STORE
}

extern "C" void kernel_launch(void* const* d_in, const int* in_sizes, int n_in,
                              void* d_out, int out_size) {
    const float* keys = (const float*)d_in[0];   // (1,32,4096,128)
    const float* vals = (const float*)d_in[1];   // (1,32,4096,128)
    const float* attn = (const float*)d_in[2];   // (1,32,1024,4096)
    float* out = (float*)d_out;                  // 2*32*822*128 f32

    k_colsum<<<NBLK, NTHR>>>(attn);
    k_tail<<<NBLK, NTHR>>>((const float4*)keys, (const float4*)vals,
                           (float4*)out);
}

// round 17
// speedup vs baseline: 1.0380x; 1.0380x over previous
#include <cuda_runtime.h>

// Problem constants (B=1, H=32, Q=1024, S=4096, D=128)
#define SEQ      4096
#define ROWS     32768      // B*H*Q rows of attn_weights
#define START    4
#define HEAVY    409        // int(4096*0.1)
#define RSTART   3687       // 4096 - min(409,512)
#define NCAND    3683       // RSTART - START
#define NKEEP    822        // 4 + 409 + 409
#define HEADS    32
#define NBLK     148        // one exact wave
#define NTHR     1024
#define NFIX     413        // START + recent rows (selection-independent)
#define TOTAL_F  (2*HEADS*NFIX*32)    // fixed-gather float4  = 845824
#define TOTAL_H  (2*HEADS*HEAVY*32)   // heavy-gather float4  = 837632
#define FSTRIDE  (NBLK*NTHR)          // 151552 (6 chunks cover TOTAL_F)
#define SETCAP   512        // max selected-bin tie set (expected ~5-20)

// Scratch. g_sums is atomically accumulated so it MUST be zero at entry:
// in k_tail, the last block to FINISH LOADING g_sums re-zeroes it at its
// end (arrive counter, no waiting). g_done reset by that same block.
__device__ double g_sums[SEQ];
__device__ int    g_done;

// ================= Kernel 1: column sums (512 MB PURE READ stream) =========
// 148 blocks, contiguous row range each (measured ~80us @ ~83% DRAM —
// at the practical HBM ceiling). Thread t owns columns [4t,4t+4) via
// float4; 8 front-batched LDG.128 (MLP=8); __ldcs (no reuse). fp32 over 32
// rows flushed into fp64 keeps the mean accurate to ~1e-8 rel (top-k
// boundary gap ~1e-5); fp64 atomicAdd ordering noise ~1e-13 — selection
// identical to reference (rel_err 0.0 in all rounds).
__global__ void __launch_bounds__(NTHR, 1) k_colsum(const float* __restrict__ w) {
    const int t = threadIdx.x;
    const int b = blockIdx.x;
    const int r0 = (int)((long long)ROWS * b / NBLK);
    const int r1 = (int)((long long)ROWS * (b + 1) / NBLK);
    const float4* __restrict__ w4 = (const float4*)w + t;
    double a0 = 0, a1 = 0, a2 = 0, a3 = 0;
    float  c0 = 0, c1 = 0, c2 = 0, c3 = 0;
    int row = r0, grp = 0;
    for (; row + 8 <= r1; row += 8) {
        float4 v[8];
        #pragma unroll
        for (int k = 0; k < 8; k++)
            v[k] = __ldcs(&w4[(size_t)(row + k) * 1024]);
        float s0x = (v[0].x + v[1].x) + (v[2].x + v[3].x);
        float s1x = (v[4].x + v[5].x) + (v[6].x + v[7].x);
        float s0y = (v[0].y + v[1].y) + (v[2].y + v[3].y);
        float s1y = (v[4].y + v[5].y) + (v[6].y + v[7].y);
        float s0z = (v[0].z + v[1].z) + (v[2].z + v[3].z);
        float s1z = (v[4].z + v[5].z) + (v[6].z + v[7].z);
        float s0w = (v[0].w + v[1].w) + (v[2].w + v[3].w);
        float s1w = (v[4].w + v[5].w) + (v[6].w + v[7].w);
        c0 += s0x + s1x;  c1 += s0y + s1y;
        c2 += s0z + s1z;  c3 += s0w + s1w;
        if (++grp == 4) {                 // flush every 32 rows
            a0 += c0; a1 += c1; a2 += c2; a3 += c3;
            c0 = c1 = c2 = c3 = 0.f; grp = 0;
        }
    }
    for (; row < r1; row++) {
        float4 v = __ldcs(&w4[(size_t)row * 1024]);
        c0 += v.x; c1 += v.y; c2 += v.z; c3 += v.w;
    }
    a0 += c0; a1 += c1; a2 += c2; a3 += c3;
    int s = 4 * t;
    atomicAdd(&g_sums[s + 0], a0);
    atomicAdd(&g_sums[s + 1], a1);
    atomicAdd(&g_sums[s + 2], a2);
    atomicAdd(&g_sums[s + 3], a3);
}

// Fixed-gather addressing (sinks + recent window, selection-independent).
__device__ __forceinline__ bool fg_addr(int v,
                                        const float4* __restrict__ keys,
                                        const float4* __restrict__ vals,
                                        const float4** src, size_t* oi) {
    if (v >= TOTAL_F) return false;
    int d4  = v & 31;
    int row = v >> 5;
    int tensor = row / (HEADS * NFIX);
    int rem = row - tensor * (HEADS * NFIX);
    int h   = rem / NFIX;
    int p   = rem - h * NFIX;                 // 0..412
    int r   = (p < START) ? p : p + HEAVY;    // output row (keep order)
    int s   = (p < START) ? p : (RSTART + p - START);
    const float4* sp = tensor ? vals : keys;
    *src = &sp[(((size_t)h * SEQ + s) << 5) + d4];
    *oi  = (((size_t)(tensor * HEADS + h) * NKEEP + r) << 5) + d4;
    return true;
}

// ==== Kernel 2: select (shift-binned histogram) || 2-deep pipelined FG =====
// Select identical to R15/R16 (proven): ONE shift-binned histogram,
// monotonic in the u64 key (positive doubles bit-order isomorphic); tie
// subset exact-ranked with the reference comparator (value desc, index
// asc) == jax.lax.top_k. Two fixed-gather chunks are kept in flight at all
// times, with loads/stores staggered across the select phases.
__global__ void __launch_bounds__(NTHR, 1)
k_tail(const float4* __restrict__ keys,
       const float4* __restrict__ vals,
       float4* __restrict__ out) {
    __shared__ unsigned long long sj[NCAND];
    __shared__ int  hist[2048];
    __shared__ int  s_keep[NKEEP];
    __shared__ int  warpsum[32];
    __shared__ unsigned long long redmin[32], redmax[32];
    __shared__ unsigned long long s_kmin;
    __shared__ int  s_shift;
    __shared__ int  s_bin, s_R, s_setcnt, s_zero;
    __shared__ int  s_setidx[SETCAP];
    __shared__ unsigned char s_take[SETCAP];

    const int t = threadIdx.x;
    const int b = blockIdx.x;
    const int lane = t & 31, w = t >> 5;

    // 2-deep fixed-gather pipeline state (slots A and B).
    int fgvA = b * NTHR + t;
    int fgvB = fgvA + FSTRIDE;
    const float4* fsA; const float4* fsB;
    size_t foA, foB; float4 fdA, fdB; bool fokA, fokB;
    #define FGA_LOAD()  do { fokA = fg_addr(fgvA, keys, vals, &fsA, &foA); \
                             if (fokA) fdA = __ldcs(fsA); } while (0)
    #define FGB_LOAD()  do { fokB = fg_addr(fgvB, keys, vals, &fsB, &foB); \
                             if (fokB) fdB = __ldcs(fsB); } while (0)
    #define FGA_STORE() do { if (fokA) out[foA] = fdA; fgvA += 2*FSTRIDE; } while (0)
    #define FGB_STORE() do { if (fokB) out[foB] = fdB; fgvB += 2*FSTRIDE; } while (0)

    // ---- chunks 0,1 in flight; load sums (minmax fused) + zero hist -------
    FGA_LOAD(); FGB_LOAD();
    for (int i = t; i < 2048; i += NTHR) hist[i] = 0;
    {
        unsigned long long mn = ~0ULL, mx = 0ULL;
        for (int k = t; k < NCAND; k += NTHR) {
            unsigned long long key =
                __double_as_longlong(__ldcg(&g_sums[START + k]));
            sj[k] = key;
            mn = min(mn, key); mx = max(mx, key);
        }
        #pragma unroll
        for (int o = 16; o; o >>= 1) {
            mn = min(mn, __shfl_xor_sync(0xFFFFFFFFu, mn, o));
            mx = max(mx, __shfl_xor_sync(0xFFFFFFFFu, mx, o));
        }
        if (lane == 0) { redmin[w] = mn; redmax[w] = mx; }
    }
    if (t == 0) s_setcnt = 0;
    __syncthreads();
    if (t == 0) {
        __threadfence();
        s_zero = (atomicAdd(&g_done, 1) == NBLK - 1) ? 1 : 0;
    }
    if (w == 0) {
        unsigned long long mn = redmin[lane], mx = redmax[lane];
        #pragma unroll
        for (int o = 16; o; o >>= 1) {
            mn = min(mn, __shfl_xor_sync(0xFFFFFFFFu, mn, o));
            mx = max(mx, __shfl_xor_sync(0xFFFFFFFFu, mx, o));
        }
        if (lane == 0) {
            s_kmin = mn;
            unsigned long long width = mx - mn;
            int bits = 64 - __clzll(width | 1ULL);
            s_shift = (bits > 11) ? (bits - 11) : 0;
        }
    }
    __syncthreads();
    FGA_STORE(); FGA_LOAD();                     // c0 -> out, c2 in flight
    const unsigned long long kmin = s_kmin;
    const int sh = s_shift;
    #define BINOF(key) ((int)(((key) - kmin) >> sh))

    // ---- single 2048-bin histogram ----------------------------------------
    for (int k = t; k < NCAND; k += NTHR)
        atomicAdd(&hist[BINOF(sj[k])], 1);
    __syncthreads();
    FGB_STORE(); FGB_LOAD();                     // c1 -> out, c3 in flight

    // ---- suffix scan over bins (descending) -> threshold bin + residual R --
    {
        const int r0 = 2 * t, r1 = 2 * t + 1;
        const int v0 = hist[2047 - r0];
        const int v1 = hist[2047 - r1];
        const int pair = v0 + v1;
        int v = pair;
        #pragma unroll
        for (int o = 1; o < 32; o <<= 1) {
            int n = __shfl_up_sync(0xFFFFFFFFu, v, o);
            if (lane >= o) v += n;
        }
        if (lane == 31) warpsum[w] = v;
        __syncthreads();
        if (w == 0) {
            int s = warpsum[lane];
            #pragma unroll
            for (int o = 1; o < 32; o <<= 1) {
                int n = __shfl_up_sync(0xFFFFFFFFu, s, o);
                if (lane >= o) s += n;
            }
            warpsum[lane] = s;
        }
        __syncthreads();
        const int excl = v - pair + (w > 0 ? warpsum[w - 1] : 0);
        const int T0 = excl + v0;
        const int T1 = excl + pair;
        const int R = HEAVY;
        if (T0 - v0 < R && R <= T0) { s_bin = 2047 - r0; s_R = R - (T0 - v0); }
        if (T1 - v1 < R && R <= T1) { s_bin = 2047 - r1; s_R = R - (T1 - v1); }
        __syncthreads();
    }
    FGA_STORE(); FGA_LOAD();                     // c2 -> out, c4 in flight
    const int selbin = s_bin;
    const int R = s_R;

    // ---- exact tie subset within the threshold bin -------------------------
    for (int k = t; k < NCAND; k += NTHR) {
        if (BINOF(sj[k]) == selbin) {
            int p = atomicAdd(&s_setcnt, 1);
            if (p < SETCAP) s_setidx[p] = k;
        }
    }
    __syncthreads();
    FGB_STORE(); FGB_LOAD();                     // c3 -> out, c5 in flight
    const int setcnt = min(s_setcnt, SETCAP);
    if (w == 0) {
        for (int m = lane; m < setcnt; m += 32) {
            int im = s_setidx[m];
            unsigned long long km = sj[im];
            int rk = 0;
            for (int j = 0; j < setcnt; j++) {
                int ij = s_setidx[j];
                unsigned long long kj = sj[ij];
                rk += (kj > km || (kj == km && ij < im)) ? 1 : 0;
            }
            s_take[m] = (rk < R) ? 1 : 0;
        }
    }
    __syncthreads();
    FGA_STORE();                                 // c4 -> out

    // ---- build full sorted keep list ---------------------------------------
    // keep = [0..3] ++ heavy(sorted asc) ++ [3687..4095] (globally sorted)
    {
        int base = 4 * t;
        int f[4], loc = 0;
        #pragma unroll
        for (int k = 0; k < 4; k++) {
            int c = base + k;
            int fl = 0;
            if (c < NCAND) {
                int bc = BINOF(sj[c]);
                if (bc > selbin) fl = 1;
                else if (bc == selbin) {
                    for (int m = 0; m < setcnt; m++)
                        if (s_setidx[m] == c) { fl = s_take[m]; break; }
                }
            }
            f[k] = fl; loc += fl;
        }
        int v = loc;
        #pragma unroll
        for (int o = 1; o < 32; o <<= 1) {
            int n = __shfl_up_sync(0xFFFFFFFFu, v, o);
            if (lane >= o) v += n;
        }
        if (lane == 31) warpsum[w] = v;
        __syncthreads();
        if (w == 0) {
            int s = warpsum[lane];
            #pragma unroll
            for (int o = 1; o < 32; o <<= 1) {
                int n = __shfl_up_sync(0xFFFFFFFFu, s, o);
                if (lane >= o) s += n;
            }
            warpsum[lane] = s;
        }
        __syncthreads();
        int pos = START + v - loc + (w > 0 ? warpsum[w - 1] : 0);
        #pragma unroll
        for (int k = 0; k < 4; k++) {
            if (f[k]) { s_keep[pos] = START + base + k; pos++; }
        }
        if (t < START) s_keep[t] = t;
        if (t < SEQ - RSTART) s_keep[START + HEAVY + t] = RSTART + t;
    }
    FGB_STORE();                                 // c5 -> out (last fixed)
    __syncthreads();

    // ---- Phase D: heavy gather (27 MB), unroll-4 (proven form) ------------
    {
        const int stride = NBLK * NTHR;          // 151552
        int v = b * NTHR + t;
        for (; v + 3 * stride < TOTAL_H; v += 4 * stride) {
            float4 d[4];
            size_t oidx[4];
            #pragma unroll
            for (int k = 0; k < 4; k++) {
                int vv  = v + k * stride;
                int d4  = vv & 31;
                int row = vv >> 5;
                int tensor = row / (HEADS * HEAVY);
                int rem = row - tensor * (HEADS * HEAVY);
                int h   = rem / HEAVY;
                int q   = rem - h * HEAVY;       // heavy slot 0..408
                int s   = s_keep[START + q];
                const float4* __restrict__ src = tensor ? vals : keys;
                d[k] = __ldcs(&src[(((size_t)h * SEQ + s) << 5) + d4]);
                oidx[k] = (((size_t)(tensor * HEADS + h) * NKEEP + (START + q)) << 5) + d4;
            }
            #pragma unroll
            for (int k = 0; k < 4; k++) out[oidx[k]] = d[k];
        }
        for (; v < TOTAL_H; v += stride) {
            int d4  = v & 31;
            int row = v >> 5;
            int tensor = row / (HEADS * HEAVY);
            int rem = row - tensor * (HEADS * HEAVY);
            int h   = rem / HEAVY;
            int q   = rem - h * HEAVY;
            int s   = s_keep[START + q];
            const float4* __restrict__ src = tensor ? vals : keys;
            out[(((size_t)(tensor * HEADS + h) * NKEEP + (START + q)) << 5) + d4] =
                __ldcs(&src[(((size_t)h * SEQ + s) << 5) + d4]);
        }
    }

    // ---- epilogue: designated block re-zeroes g_sums for next call --------
    __syncthreads();
    if (s_zero) {
        for (int i = t; i < SEQ; i += NTHR) g_sums[i] = 0.0;
        if (t == 0) g_done = 0;
    }
    #undef BINOF
    #undef FGA_LOAD
    #undef FGB_LOAD
    #undef FGA_STORE
    #undef FGB_STORE
}

extern "C" void kernel_launch(void* const* d_in, const int* in_sizes, int n_in,
                              void* d_out, int out_size) {
    const float* keys = (const float*)d_in[0];   // (1,32,4096,128)
    const float* vals = (const float*)d_in[1];   // (1,32,4096,128)
    const float* attn = (const float*)d_in[2];   // (1,32,1024,4096)
    float* out = (float*)d_out;                  // 2*32*822*128 f32

    k_colsum<<<NBLK, NTHR>>>(attn);
    k_tail<<<NBLK, NTHR>>>((const float4*)keys, (const float4*)vals,
                           (float4*)out);
}